// round 8
// baseline (speedup 1.0000x reference)
#include <cuda_runtime.h>
#include <cuda_bf16.h>
#include <cstdint>
#include <math.h>

#define D_MODEL 768
#define NUM_HEADS 12
#define D_HEAD 64
#define NQ 8
#define BATCH 16
#define P_TOK 197
#define M_ROWS (BATCH * P_TOK)       // 3152
#define M_PAD 3200                   // 25 * 128
#define PAIRS (BATCH * BATCH)        // 256
#define OUT_ROWS (PAIRS * NQ)        // 2048
#define LN_EPS 1e-5f
#define TILE_LD 68

// GEMM tiling
#define BM 128
#define BN 128
#define BK 32
#define LDA 40
#define MAT_B (128 * LDA * 2)
#define STAGE_B (4 * MAT_B)

#define NX4 (M_PAD * D_MODEL / 4)
#define NW4 (D_MODEL * D_MODEL / 4)
#define NP4 (P_TOK * D_MODEL / 4)        // dpos float4 count

// ---------------- scratch (device globals) ------------------------------------
__device__ float g_qpre[NQ * D_MODEL];
__device__ float g_qln[NQ * D_MODEL];
__device__ float g_kv[M_ROWS * D_MODEL];
__device__ float g_s1[M_ROWS];
__device__ float g_s2[M_ROWS];
__device__ float g_dpos[P_TOK * D_MODEL];
__device__ float g_dsp[NUM_HEADS * NQ * 200];
__device__ __nv_bfloat16 g_xh[M_PAD * D_MODEL];
__device__ __nv_bfloat16 g_xl[M_PAD * D_MODEL];
__device__ __nv_bfloat16 g_wh[D_MODEL * D_MODEL];
__device__ __nv_bfloat16 g_wl[D_MODEL * D_MODEL];
__device__ __nv_bfloat16 g_owh[D_MODEL * D_MODEL];
__device__ __nv_bfloat16 g_owl[D_MODEL * D_MODEL];
__device__ __nv_bfloat16 g_ach[OUT_ROWS * D_MODEL];
__device__ __nv_bfloat16 g_acl[OUT_ROWS * D_MODEL];
__device__ float g_m[2 * BATCH * NUM_HEADS * NQ];
__device__ float g_z[2 * BATCH * NUM_HEADS * NQ];
__device__ float g_a[2 * BATCH * NUM_HEADS * NQ * D_HEAD];

// ---------------- PTX helpers --------------------------------------------------
__device__ __forceinline__ uint32_t smem_u32(const void* p) {
    uint32_t a;
    asm("{ .reg .u64 t; cvta.to.shared.u64 t, %1; cvt.u32.u64 %0, t; }" : "=r"(a) : "l"(p));
    return a;
}
__device__ __forceinline__ void cp_async16(uint32_t s, const void* g) {
    asm volatile("cp.async.cg.shared.global [%0], [%1], 16;" :: "r"(s), "l"(g));
}
#define CP_COMMIT() asm volatile("cp.async.commit_group;")
#define CP_WAIT(n)  asm volatile("cp.async.wait_group %0;" :: "n"(n))
#define LDMX4(r, addr) \
    asm volatile("ldmatrix.sync.aligned.m8n8.x4.shared.b16 {%0,%1,%2,%3}, [%4];" \
        : "=r"((r)[0]), "=r"((r)[1]), "=r"((r)[2]), "=r"((r)[3]) : "r"(addr))
#define MMA_BF16(cr, a, b0, b1) \
    asm volatile("mma.sync.aligned.m16n8k16.row.col.f32.bf16.bf16.f32 " \
        "{%0,%1,%2,%3}, {%4,%5,%6,%7}, {%8,%9}, {%0,%1,%2,%3};" \
        : "+f"((cr)[0]), "+f"((cr)[1]), "+f"((cr)[2]), "+f"((cr)[3]) \
        : "r"((a)[0]), "r"((a)[1]), "r"((a)[2]), "r"((a)[3]), "r"(b0), "r"(b1))

// ---------------- split helpers ------------------------------------------------
__device__ __forceinline__ void split4(float4 v, ushort4& hi, ushort4& lo) {
    __nv_bfloat16 hx = __float2bfloat16_rn(v.x);
    __nv_bfloat16 hy = __float2bfloat16_rn(v.y);
    __nv_bfloat16 hz = __float2bfloat16_rn(v.z);
    __nv_bfloat16 hw = __float2bfloat16_rn(v.w);
    hi = make_ushort4(__bfloat16_as_ushort(hx), __bfloat16_as_ushort(hy),
                      __bfloat16_as_ushort(hz), __bfloat16_as_ushort(hw));
    lo = make_ushort4(
        __bfloat16_as_ushort(__float2bfloat16_rn(v.x - __bfloat162float(hx))),
        __bfloat16_as_ushort(__float2bfloat16_rn(v.y - __bfloat162float(hy))),
        __bfloat16_as_ushort(__float2bfloat16_rn(v.z - __bfloat162float(hz))),
        __bfloat16_as_ushort(__float2bfloat16_rn(v.w - __bfloat162float(hw))));
}

// split kv_x + kv_w, and zero the LN-stat accumulators
__global__ void split_kv_kernel(const float* __restrict__ x, const float* __restrict__ w) {
    int gi = blockIdx.x * blockDim.x + threadIdx.x;
    if (gi < M_ROWS) { g_s1[gi] = 0.0f; g_s2[gi] = 0.0f; }
    ushort4 hi, lo;
    if (gi < NX4) {
        int row = gi / (D_MODEL / 4);
        float4 v = (row < M_ROWS) ? ((const float4*)x)[gi] : make_float4(0.f, 0.f, 0.f, 0.f);
        split4(v, hi, lo);
        ((ushort4*)g_xh)[gi] = hi;
        ((ushort4*)g_xl)[gi] = lo;
    } else {
        int wi = gi - NX4;
        if (wi < NW4) {
            split4(((const float4*)w)[wi], hi, lo);
            ((ushort4*)g_wh)[wi] = hi;
            ((ushort4*)g_wl)[wi] = lo;
        }
    }
}
__global__ void splitw_kernel(const float* __restrict__ w,
                              __nv_bfloat16* __restrict__ dh,
                              __nv_bfloat16* __restrict__ dl) {
    int i4 = blockIdx.x * blockDim.x + threadIdx.x;
    ushort4 hi, lo;
    split4(((const float4*)w)[i4], hi, lo);
    ((ushort4*)dh)[i4] = hi;
    ((ushort4*)dl)[i4] = lo;
}

// ---------------- tensor-core GEMM (+ optional LN stats) -----------------------
__global__ __launch_bounds__(256) void gemm_bf16(
    const __nv_bfloat16* __restrict__ Agh, const __nv_bfloat16* __restrict__ Agl,
    const __nv_bfloat16* __restrict__ Bgh, const __nv_bfloat16* __restrict__ Bgl,
    const float* __restrict__ bias, float* __restrict__ C, int Mvalid, int do_stats) {
    extern __shared__ char sm[];
    __shared__ float rs1[BM], rs2[BM];
    uint32_t sbase = smem_u32(sm);
    int tid = threadIdx.x, lane = tid & 31, wid = tid >> 5;
    int wm = wid & 3, wn = wid >> 2;
    int bm = blockIdx.y * BM, bn = blockIdx.x * BN;

    if (do_stats) {
        for (int i = tid; i < BM; i += 256) { rs1[i] = 0.0f; rs2[i] = 0.0f; }
    }

    float c[2][8][4];
    #pragma unroll
    for (int i = 0; i < 2; ++i)
        #pragma unroll
        for (int j = 0; j < 8; ++j)
            #pragma unroll
            for (int k = 0; k < 4; ++k) c[i][j][k] = 0.0f;

    int lrow = tid >> 2, lc = tid & 3;

    auto ld_stage = [&](int kc, int s) {
        uint32_t st = sbase + s * STAGE_B;
        #pragma unroll
        for (int t = 0; t < 2; ++t) {
            int row = lrow + t * 64;
            uint32_t doff = (uint32_t)(row * 80 + lc * 16);
            size_t ga = (size_t)(bm + row) * D_MODEL + kc * BK + lc * 8;
            size_t gb = (size_t)(bn + row) * D_MODEL + kc * BK + lc * 8;
            cp_async16(st + doff,             Agh + ga);
            cp_async16(st + MAT_B + doff,     Agl + ga);
            cp_async16(st + 2 * MAT_B + doff, Bgh + gb);
            cp_async16(st + 3 * MAT_B + doff, Bgl + gb);
        }
    };

    auto compute = [&](int s) {
        uint32_t st = sbase + s * STAGE_B;
        int arow = ((lane >> 3) & 1) * 8 + (lane & 7);
        int acolb = (lane >> 4) * 8;
        int brow = (lane >> 4) * 8 + (lane & 7);
        int bcolb = ((lane >> 3) & 1) * 8;
        #pragma unroll
        for (int ks = 0; ks < 2; ++ks) {
            uint32_t ah[2][4], al[2][4], bh[4][4], bl[4][4];
            #pragma unroll
            for (int mt = 0; mt < 2; ++mt) {
                uint32_t ad = st + (uint32_t)((wm * 32 + mt * 16 + arow) * 80 +
                                              (ks * 16 + acolb) * 2);
                LDMX4(ah[mt], ad);
                LDMX4(al[mt], ad + MAT_B);
            }
            #pragma unroll
            for (int nt2 = 0; nt2 < 4; ++nt2) {
                uint32_t bd = st + 2 * MAT_B + (uint32_t)((wn * 64 + nt2 * 16 + brow) * 80 +
                                                          (ks * 16 + bcolb) * 2);
                LDMX4(bh[nt2], bd);
                LDMX4(bl[nt2], bd + MAT_B);
            }
            #pragma unroll
            for (int mt = 0; mt < 2; ++mt)
                #pragma unroll
                for (int nt = 0; nt < 8; ++nt) {
                    int n2 = nt >> 1, pr = (nt & 1) * 2;
                    MMA_BF16(c[mt][nt], ah[mt], bh[n2][pr], bh[n2][pr + 1]);
                    MMA_BF16(c[mt][nt], ah[mt], bl[n2][pr], bl[n2][pr + 1]);
                    MMA_BF16(c[mt][nt], al[mt], bh[n2][pr], bh[n2][pr + 1]);
                }
        }
    };

    ld_stage(0, 0);
    CP_COMMIT();
    const int KC = D_MODEL / BK;
    for (int kc = 0; kc < KC; ++kc) {
        int s = kc & 1;
        if (kc < KC - 1) {
            ld_stage(kc + 1, s ^ 1);
            CP_COMMIT();
            CP_WAIT(1);
        } else {
            CP_WAIT(0);
        }
        __syncthreads();
        compute(s);
        __syncthreads();
    }

    #pragma unroll
    for (int mt = 0; mt < 2; ++mt) {
        int lr0 = wm * 32 + mt * 16 + (lane >> 2);
        int r0 = bm + lr0;
        float sA0 = 0.f, sQ0 = 0.f, sA1 = 0.f, sQ1 = 0.f;
        #pragma unroll
        for (int nt = 0; nt < 8; ++nt) {
            int col = bn + wn * 64 + nt * 8 + (lane & 3) * 2;
            float b0 = bias[col], b1 = bias[col + 1];
            float v00 = c[mt][nt][0] + b0, v01 = c[mt][nt][1] + b1;
            float v10 = c[mt][nt][2] + b0, v11 = c[mt][nt][3] + b1;
            if (r0 < Mvalid) {
                C[(size_t)r0 * D_MODEL + col]     = v00;
                C[(size_t)r0 * D_MODEL + col + 1] = v01;
            }
            if (r0 + 8 < Mvalid) {
                C[(size_t)(r0 + 8) * D_MODEL + col]     = v10;
                C[(size_t)(r0 + 8) * D_MODEL + col + 1] = v11;
            }
            sA0 += v00 + v01; sQ0 += v00 * v00 + v01 * v01;
            sA1 += v10 + v11; sQ1 += v10 * v10 + v11 * v11;
        }
        if (do_stats) {
            atomicAdd(&rs1[lr0], sA0); atomicAdd(&rs2[lr0], sQ0);
            atomicAdd(&rs1[lr0 + 8], sA1); atomicAdd(&rs2[lr0 + 8], sQ1);
        }
    }
    if (do_stats) {
        __syncthreads();
        for (int i = tid; i < BM; i += 256) {
            int r = bm + i;
            if (r < M_ROWS) {
                atomicAdd(&g_s1[r], rs1[i]);
                atomicAdd(&g_s2[r], rs2[i]);
            }
        }
    }
}

// ---------------- q GEMM + LN --------------------------------------------------
__global__ __launch_bounds__(256) void qgemm_kernel(const float* __restrict__ qx,
                                                    const float* __restrict__ qw,
                                                    const float* __restrict__ qb) {
    int gw = blockIdx.x * 8 + (threadIdx.x >> 5);
    int lane = threadIdx.x & 31;
    int row = gw / D_MODEL, col = gw - row * D_MODEL;
    const float4* x4 = (const float4*)(qx + (size_t)row * D_MODEL);
    const float4* w4 = (const float4*)(qw + (size_t)col * D_MODEL);
    float acc = 0.0f;
    #pragma unroll
    for (int i = 0; i < 6; ++i) {
        float4 a = x4[lane + 32 * i];
        float4 b = w4[lane + 32 * i];
        acc += a.x * b.x + a.y * b.y + a.z * b.z + a.w * b.w;
    }
    #pragma unroll
    for (int off = 16; off > 0; off >>= 1) acc += __shfl_xor_sync(0xffffffffu, acc, off);
    if (lane == 0) g_qpre[row * D_MODEL + col] = acc + qb[col];
}
__global__ void qln_kernel(const float* __restrict__ lw, const float* __restrict__ lb) {
    int row = blockIdx.x;
    int t = threadIdx.x;
    const float* x = g_qpre + row * D_MODEL;
    float v0 = x[t], v1 = x[t + 256], v2 = x[t + 512];
    __shared__ float red[256];
    red[t] = v0 + v1 + v2;
    __syncthreads();
    for (int s = 128; s > 0; s >>= 1) { if (t < s) red[t] += red[t + s]; __syncthreads(); }
    float mean = red[0] * (1.0f / D_MODEL);
    __syncthreads();
    float d0 = v0 - mean, d1 = v1 - mean, d2 = v2 - mean;
    red[t] = d0 * d0 + d1 * d1 + d2 * d2;
    __syncthreads();
    for (int s = 128; s > 0; s >>= 1) { if (t < s) red[t] += red[t + s]; __syncthreads(); }
    float rstd = rsqrtf(red[0] * (1.0f / D_MODEL) + LN_EPS);
    g_qln[row * D_MODEL + t]       = d0 * rstd * lw[t]       + lb[t];
    g_qln[row * D_MODEL + t + 256] = d1 * rstd * lw[t + 256] + lb[t + 256];
    g_qln[row * D_MODEL + t + 512] = d2 * rstd * lw[t + 512] + lb[t + 512];
}

// ---------------- dpos = pos[P:] - pos[:P] ------------------------------------
__global__ void dpos_kernel(const float* __restrict__ pos) {
    int i4 = blockIdx.x * blockDim.x + threadIdx.x;
    if (i4 >= NP4) return;
    float4 a = ((const float4*)pos)[NP4 + i4];
    float4 b = ((const float4*)pos)[i4];
    float4 v = make_float4(a.x - b.x, a.y - b.y, a.z - b.z, a.w - b.w);
    ((float4*)g_dpos)[i4] = v;
}

// ---------------- dsp[h][q][p] = 0.125 * q_h . dpos[p,h] ----------------------
__global__ __launch_bounds__(256) void dsp_kernel() {
    int h = blockIdx.x;
    int tid = threadIdx.x;
    __shared__ float4 sq[NQ][D_HEAD / 4];
    if (tid < NQ * (D_HEAD / 4)) {
        int q = tid >> 4, d4 = tid & 15;
        sq[q][d4] = ((const float4*)(g_qln + q * D_MODEL + h * D_HEAD))[d4];
    }
    __syncthreads();
    int p = tid;
    if (p >= P_TOK) return;
    float acc[NQ];
    #pragma unroll
    for (int q = 0; q < NQ; ++q) acc[q] = 0.0f;
    const float4* dp4 = (const float4*)(g_dpos + (size_t)p * D_MODEL + h * D_HEAD);
    #pragma unroll
    for (int d4 = 0; d4 < D_HEAD / 4; ++d4) {
        float4 dp = dp4[d4];
        #pragma unroll
        for (int q = 0; q < NQ; ++q) {
            float4 qv = sq[q][d4];
            acc[q] += dp.x * qv.x + dp.y * qv.y + dp.z * qv.z + dp.w * qv.w;
        }
    }
    #pragma unroll
    for (int q = 0; q < NQ; ++q)
        g_dsp[(h * NQ + q) * 200 + p] = 0.125f * acc[q];
}

// ---------------- attention: both halves per (b,h) block ----------------------
__global__ __launch_bounds__(256) void attn_kernel(const float* __restrict__ pos,
                                                   const float* __restrict__ lw,
                                                   const float* __restrict__ lb) {
    extern __shared__ float sm_tile[];   // [P_TOK][TILE_LD]
    int b = blockIdx.x, h = blockIdx.y;
    int tid = threadIdx.x;
    int w = tid >> 5, lane = tid & 31;

    __shared__ float4 qh4[NQ][D_HEAD / 4];
    __shared__ float sraw[NQ][200];
    __shared__ float e[NQ][200];
    __shared__ float smean[200], srstd[200];

    // per-row LN stats from gemm1 accumulators
    if (tid < P_TOK) {
        float mean = g_s1[b * P_TOK + tid] * (1.0f / D_MODEL);
        float var = g_s2[b * P_TOK + tid] * (1.0f / D_MODEL) - mean * mean;
        smean[tid] = mean;
        srstd[tid] = rsqrtf(var + LN_EPS);
    }
    for (int idx = tid; idx < NQ * (D_HEAD / 4); idx += 256) {
        int q = idx >> 4, d4 = idx & 15;
        qh4[q][d4] = ((const float4*)(g_qln + q * D_MODEL + h * D_HEAD))[d4];
    }
    __syncthreads();

    // tile = LN(kv) * lw + lb + pos(half0)
    const float4* lw4 = (const float4*)(lw + h * D_HEAD);
    const float4* lb4 = (const float4*)(lb + h * D_HEAD);
    for (int idx = tid; idx < P_TOK * (D_HEAD / 4); idx += 256) {
        int p = idx >> 4, d4 = idx & 15;
        int row = b * P_TOK + p;
        float m = smean[p], r = srstd[p];
        float4 raw = ((const float4*)(g_kv + (size_t)row * D_MODEL + h * D_HEAD))[d4];
        float4 pv = ((const float4*)(pos + (size_t)p * D_MODEL + h * D_HEAD))[d4];
        float4 wv = lw4[d4], bv = lb4[d4];
        float4 out;
        out.x = (raw.x - m) * r * wv.x + bv.x + pv.x;
        out.y = (raw.y - m) * r * wv.y + bv.y + pv.y;
        out.z = (raw.z - m) * r * wv.z + bv.z + pv.z;
        out.w = (raw.w - m) * r * wv.w + bv.w + pv.w;
        *(float4*)(sm_tile + p * TILE_LD + d4 * 4) = out;
    }
    __syncthreads();

    // ---- half 0: dot + softmax ----
    {
        int q = w;
        float mx = -1e30f;
        for (int p = lane; p < P_TOK; p += 32) {
            const float4* tp4 = (const float4*)(sm_tile + p * TILE_LD);
            float s = 0.0f;
            #pragma unroll
            for (int k = 0; k < D_HEAD / 4; ++k) {
                float4 t = tp4[k];
                float4 qv = qh4[q][k];
                s += t.x * qv.x + t.y * qv.y + t.z * qv.z + t.w * qv.w;
            }
            s *= 0.125f;
            sraw[q][p] = s;
            mx = fmaxf(mx, s);
        }
        #pragma unroll
        for (int off = 16; off > 0; off >>= 1) mx = fmaxf(mx, __shfl_xor_sync(0xffffffffu, mx, off));
        float sum = 0.0f;
        for (int p = lane; p < P_TOK; p += 32) {
            float t = __expf(sraw[q][p] - mx);
            e[q][p] = t;
            sum += t;
        }
        #pragma unroll
        for (int off = 16; off > 0; off >>= 1) sum += __shfl_xor_sync(0xffffffffu, sum, off);
        if (lane == 0) {
            int idx = (b * NUM_HEADS + h) * NQ + q;
            g_m[idx] = mx;
            g_z[idx] = sum;
        }
    }
    __syncthreads();

    // ---- half 0: A ----
    for (int ii = tid; ii < NQ * D_HEAD; ii += 256) {
        int q = ii >> 6, d = ii & 63;
        float acc = 0.0f;
        const float* tcol = sm_tile + d;
        #pragma unroll 4
        for (int p = 0; p < 196; p += 4) {
            float4 ev = *(const float4*)&e[q][p];
            acc += ev.x * tcol[p * TILE_LD] + ev.y * tcol[(p + 1) * TILE_LD] +
                   ev.z * tcol[(p + 2) * TILE_LD] + ev.w * tcol[(p + 3) * TILE_LD];
        }
        acc += e[q][196] * tcol[196 * TILE_LD];
        g_a[(((size_t)b * NUM_HEADS + h) * NQ + q) * D_HEAD + d] = acc;
    }
    __syncthreads();

    // ---- switch to half 1: tile += dpos ----
    for (int idx = tid; idx < P_TOK * (D_HEAD / 4); idx += 256) {
        int p = idx >> 4, d4 = idx & 15;
        float4 dv = ((const float4*)(g_dpos + (size_t)p * D_MODEL + h * D_HEAD))[d4];
        float4* tp = (float4*)(sm_tile + p * TILE_LD + d4 * 4);
        float4 t = *tp;
        t.x += dv.x; t.y += dv.y; t.z += dv.z; t.w += dv.w;
        *tp = t;
    }
    // half 1 scores = sraw + dsp; softmax
    {
        int q = w;
        const float* dsp = g_dsp + (h * NQ + q) * 200;
        float mx = -1e30f;
        for (int p = lane; p < P_TOK; p += 32) {
            float s = sraw[q][p] + dsp[p];
            sraw[q][p] = s;      // reuse as half-1 raw
            mx = fmaxf(mx, s);
        }
        #pragma unroll
        for (int off = 16; off > 0; off >>= 1) mx = fmaxf(mx, __shfl_xor_sync(0xffffffffu, mx, off));
        float sum = 0.0f;
        for (int p = lane; p < P_TOK; p += 32) {
            float t = __expf(sraw[q][p] - mx);
            e[q][p] = t;
            sum += t;
        }
        #pragma unroll
        for (int off = 16; off > 0; off >>= 1) sum += __shfl_xor_sync(0xffffffffu, sum, off);
        if (lane == 0) {
            int idx = ((BATCH + b) * NUM_HEADS + h) * NQ + q;
            g_m[idx] = mx;
            g_z[idx] = sum;
        }
    }
    __syncthreads();

    // ---- half 1: A ----
    for (int ii = tid; ii < NQ * D_HEAD; ii += 256) {
        int q = ii >> 6, d = ii & 63;
        float acc = 0.0f;
        const float* tcol = sm_tile + d;
        #pragma unroll 4
        for (int p = 0; p < 196; p += 4) {
            float4 ev = *(const float4*)&e[q][p];
            acc += ev.x * tcol[p * TILE_LD] + ev.y * tcol[(p + 1) * TILE_LD] +
                   ev.z * tcol[(p + 2) * TILE_LD] + ev.w * tcol[(p + 3) * TILE_LD];
        }
        acc += e[q][196] * tcol[196 * TILE_LD];
        g_a[((((size_t)BATCH + b) * NUM_HEADS + h) * NQ + q) * D_HEAD + d] = acc;
    }
}

// ---------------- merge: one block per pair, loop q ---------------------------
__global__ __launch_bounds__(192) void merge_kernel() {
    int pair = blockIdx.x;
    int i = pair >> 4, j = pair & 15;
    int tid = threadIdx.x;
    __shared__ float c1s[NQ][NUM_HEADS], c2s[NQ][NUM_HEADS];
    if (tid < NQ * NUM_HEADS) {
        int q = tid / NUM_HEADS, h = tid - q * NUM_HEADS;
        int i1 = (i * NUM_HEADS + h) * NQ + q;
        int i2 = ((BATCH + j) * NUM_HEADS + h) * NQ + q;
        float m1 = g_m[i1], m2 = g_m[i2];
        float z1 = g_z[i1], z2 = g_z[i2];
        float m = fmaxf(m1, m2);
        float e1 = __expf(m1 - m), e2 = __expf(m2 - m);
        float zinv = 1.0f / (e1 * z1 + e2 * z2);
        c1s[q][h] = e1 * zinv;
        c2s[q][h] = e2 * zinv;
    }
    __syncthreads();
    int o0 = tid * 4;
    int h = o0 >> 6, d = o0 & 63;
    #pragma unroll
    for (int q = 0; q < NQ; ++q) {
        float4 a1 = *(const float4*)(g_a + (((size_t)i * NUM_HEADS + h) * NQ + q) * D_HEAD + d);
        float4 a2 = *(const float4*)(g_a + ((((size_t)BATCH + j) * NUM_HEADS + h) * NQ + q) * D_HEAD + d);
        float w1 = c1s[q][h], w2 = c2s[q][h];
        float4 v;
        v.x = w1 * a1.x - w2 * a2.x;
        v.y = w1 * a1.y - w2 * a2.y;
        v.z = w1 * a1.z - w2 * a2.z;
        v.w = w1 * a1.w - w2 * a2.w;
        ushort4 hi, lo;
        split4(v, hi, lo);
        size_t row = (size_t)pair * NQ + q;
        ((ushort4*)(g_ach + row * D_MODEL))[tid] = hi;
        ((ushort4*)(g_acl + row * D_MODEL))[tid] = lo;
    }
}

// ---------------- launch ------------------------------------------------------
extern "C" void kernel_launch(void* const* d_in, const int* in_sizes, int n_in,
                              void* d_out, int out_size) {
    const float* q_x   = (const float*)d_in[0];
    const float* kv_x  = (const float*)d_in[1];
    const float* pos   = (const float*)d_in[2];
    const float* q_w   = (const float*)d_in[3];
    const float* q_b   = (const float*)d_in[4];
    const float* kv_w  = (const float*)d_in[5];
    const float* kv_b  = (const float*)d_in[6];
    const float* out_w = (const float*)d_in[7];
    const float* out_b = (const float*)d_in[8];
    const float* lnq_w = (const float*)d_in[9];
    const float* lnq_b = (const float*)d_in[10];
    const float* lnkv_w = (const float*)d_in[11];
    const float* lnkv_b = (const float*)d_in[12];
    float* out = (float*)d_out;

    __nv_bfloat16 *p_xh, *p_xl, *p_wh, *p_wl, *p_owh, *p_owl, *p_ach, *p_acl;
    float* p_kv;
    cudaGetSymbolAddress((void**)&p_xh, g_xh);
    cudaGetSymbolAddress((void**)&p_xl, g_xl);
    cudaGetSymbolAddress((void**)&p_wh, g_wh);
    cudaGetSymbolAddress((void**)&p_wl, g_wl);
    cudaGetSymbolAddress((void**)&p_owh, g_owh);
    cudaGetSymbolAddress((void**)&p_owl, g_owl);
    cudaGetSymbolAddress((void**)&p_ach, g_ach);
    cudaGetSymbolAddress((void**)&p_acl, g_acl);
    cudaGetSymbolAddress((void**)&p_kv, g_kv);

    static cudaStream_t s1 = nullptr, s2 = nullptr;
    static cudaEvent_t evFork = nullptr, evQ = nullptr, evW = nullptr, evSP = nullptr;
    if (!s1) {
        cudaStreamCreateWithFlags(&s1, cudaStreamNonBlocking);
        cudaStreamCreateWithFlags(&s2, cudaStreamNonBlocking);
        cudaEventCreateWithFlags(&evFork, cudaEventDisableTiming);
        cudaEventCreateWithFlags(&evQ, cudaEventDisableTiming);
        cudaEventCreateWithFlags(&evW, cudaEventDisableTiming);
        cudaEventCreateWithFlags(&evSP, cudaEventDisableTiming);
        cudaFuncSetAttribute(gemm_bf16, cudaFuncAttributeMaxDynamicSharedMemorySize, 2 * STAGE_B);
        cudaFuncSetAttribute(attn_kernel, cudaFuncAttributeMaxDynamicSharedMemorySize,
                             P_TOK * TILE_LD * sizeof(float));
    }
    int gemm_smem = 2 * STAGE_B;
    int tile_bytes = P_TOK * TILE_LD * sizeof(float);

    cudaEventRecord(evFork, 0);
    cudaStreamWaitEvent(s1, evFork, 0);
    cudaStreamWaitEvent(s2, evFork, 0);

    // s1: q path
    qgemm_kernel<<<(NQ * D_MODEL) / 8, 256, 0, s1>>>(q_x, q_w, q_b);
    qln_kernel<<<NQ, 256, 0, s1>>>(lnq_w, lnq_b);
    cudaEventRecord(evQ, s1);

    // s2: dpos -> (qln) -> dsp -> out_w split
    dpos_kernel<<<(NP4 + 255) / 256, 256, 0, s2>>>(pos);
    cudaStreamWaitEvent(s2, evQ, 0);
    dsp_kernel<<<NUM_HEADS, 256, 0, s2>>>();
    cudaEventRecord(evSP, s2);
    splitw_kernel<<<NW4 / 256, 256, 0, s2>>>(out_w, p_owh, p_owl);
    cudaEventRecord(evW, s2);

    // main chain
    split_kv_kernel<<<(NX4 + NW4 + 255) / 256, 256>>>(kv_x, kv_w);
    gemm_bf16<<<dim3(6, 25), 256, gemm_smem>>>(p_xh, p_xl, p_wh, p_wl, kv_b, p_kv, M_ROWS, 1);
    cudaStreamWaitEvent(0, evSP, 0);
    attn_kernel<<<dim3(BATCH, NUM_HEADS), 256, tile_bytes>>>(pos, lnkv_w, lnkv_b);
    merge_kernel<<<PAIRS, 192>>>();
    cudaStreamWaitEvent(0, evW, 0);
    gemm_bf16<<<dim3(6, 16), 256, gemm_smem>>>(p_ach, p_acl, p_owh, p_owl, out_b, out, OUT_ROWS, 0);
}

// round 9
// speedup vs baseline: 1.0172x; 1.0172x over previous
#include <cuda_runtime.h>
#include <cuda_bf16.h>
#include <cstdint>
#include <math.h>

#define D_MODEL 768
#define NUM_HEADS 12
#define D_HEAD 64
#define NQ 8
#define BATCH 16
#define P_TOK 197
#define M_ROWS (BATCH * P_TOK)       // 3152
#define M_PAD 3200                   // 25 * 128
#define PAIRS (BATCH * BATCH)        // 256
#define OUT_ROWS (PAIRS * NQ)        // 2048
#define LN_EPS 1e-5f
#define TILE_LD 68

// GEMM tiling
#define BM 128
#define BN 128
#define BK 32
#define LDA 40
#define MAT_B (128 * LDA * 2)
#define STAGE_B (4 * MAT_B)

#define NX4 (M_PAD * D_MODEL / 4)
#define NW4 (D_MODEL * D_MODEL / 4)
#define NP4 (P_TOK * D_MODEL / 4)

// ---------------- scratch (device globals) ------------------------------------
__device__ float g_qpre[NQ * D_MODEL];
__device__ float g_qln[NQ * D_MODEL];
__device__ float g_kv[M_ROWS * D_MODEL];
__device__ float g_s1[M_ROWS];
__device__ float g_s2[M_ROWS];
__device__ float g_dpos[P_TOK * D_MODEL];
__device__ float g_dsp[NUM_HEADS * NQ * 200];
__device__ __nv_bfloat16 g_xh[M_PAD * D_MODEL];
__device__ __nv_bfloat16 g_xl[M_PAD * D_MODEL];
__device__ __nv_bfloat16 g_wh[D_MODEL * D_MODEL];
__device__ __nv_bfloat16 g_wl[D_MODEL * D_MODEL];
__device__ __nv_bfloat16 g_owh[D_MODEL * D_MODEL];
__device__ __nv_bfloat16 g_owl[D_MODEL * D_MODEL];
__device__ __nv_bfloat16 g_ach[OUT_ROWS * D_MODEL];
__device__ __nv_bfloat16 g_acl[OUT_ROWS * D_MODEL];
__device__ float g_m[2 * BATCH * NUM_HEADS * NQ];
__device__ float g_z[2 * BATCH * NUM_HEADS * NQ];
__device__ float g_a[2 * BATCH * NUM_HEADS * NQ * D_HEAD];

// ---------------- PTX helpers --------------------------------------------------
__device__ __forceinline__ uint32_t smem_u32(const void* p) {
    uint32_t a;
    asm("{ .reg .u64 t; cvta.to.shared.u64 t, %1; cvt.u32.u64 %0, t; }" : "=r"(a) : "l"(p));
    return a;
}
__device__ __forceinline__ void cp_async16(uint32_t s, const void* g) {
    asm volatile("cp.async.cg.shared.global [%0], [%1], 16;" :: "r"(s), "l"(g));
}
#define CP_COMMIT() asm volatile("cp.async.commit_group;")
#define CP_WAIT(n)  asm volatile("cp.async.wait_group %0;" :: "n"(n))
#define LDMX4(r, addr) \
    asm volatile("ldmatrix.sync.aligned.m8n8.x4.shared.b16 {%0,%1,%2,%3}, [%4];" \
        : "=r"((r)[0]), "=r"((r)[1]), "=r"((r)[2]), "=r"((r)[3]) : "r"(addr))
#define MMA_BF16(cr, a, b0, b1) \
    asm volatile("mma.sync.aligned.m16n8k16.row.col.f32.bf16.bf16.f32 " \
        "{%0,%1,%2,%3}, {%4,%5,%6,%7}, {%8,%9}, {%0,%1,%2,%3};" \
        : "+f"((cr)[0]), "+f"((cr)[1]), "+f"((cr)[2]), "+f"((cr)[3]) \
        : "r"((a)[0]), "r"((a)[1]), "r"((a)[2]), "r"((a)[3]), "r"(b0), "r"(b1))

// ---------------- split helpers ------------------------------------------------
__device__ __forceinline__ void split4(float4 v, ushort4& hi, ushort4& lo) {
    __nv_bfloat16 hx = __float2bfloat16_rn(v.x);
    __nv_bfloat16 hy = __float2bfloat16_rn(v.y);
    __nv_bfloat16 hz = __float2bfloat16_rn(v.z);
    __nv_bfloat16 hw = __float2bfloat16_rn(v.w);
    hi = make_ushort4(__bfloat16_as_ushort(hx), __bfloat16_as_ushort(hy),
                      __bfloat16_as_ushort(hz), __bfloat16_as_ushort(hw));
    lo = make_ushort4(
        __bfloat16_as_ushort(__float2bfloat16_rn(v.x - __bfloat162float(hx))),
        __bfloat16_as_ushort(__float2bfloat16_rn(v.y - __bfloat162float(hy))),
        __bfloat16_as_ushort(__float2bfloat16_rn(v.z - __bfloat162float(hz))),
        __bfloat16_as_ushort(__float2bfloat16_rn(v.w - __bfloat162float(hw))));
}

// split kv_x + kv_w, and zero the LN-stat accumulators
__global__ void split_kv_kernel(const float* __restrict__ x, const float* __restrict__ w) {
    int gi = blockIdx.x * blockDim.x + threadIdx.x;
    if (gi < M_ROWS) { g_s1[gi] = 0.0f; g_s2[gi] = 0.0f; }
    ushort4 hi, lo;
    if (gi < NX4) {
        int row = gi / (D_MODEL / 4);
        float4 v = (row < M_ROWS) ? ((const float4*)x)[gi] : make_float4(0.f, 0.f, 0.f, 0.f);
        split4(v, hi, lo);
        ((ushort4*)g_xh)[gi] = hi;
        ((ushort4*)g_xl)[gi] = lo;
    } else {
        int wi = gi - NX4;
        if (wi < NW4) {
            split4(((const float4*)w)[wi], hi, lo);
            ((ushort4*)g_wh)[wi] = hi;
            ((ushort4*)g_wl)[wi] = lo;
        }
    }
}
__global__ void splitw_kernel(const float* __restrict__ w,
                              __nv_bfloat16* __restrict__ dh,
                              __nv_bfloat16* __restrict__ dl) {
    int i4 = blockIdx.x * blockDim.x + threadIdx.x;
    ushort4 hi, lo;
    split4(((const float4*)w)[i4], hi, lo);
    ((ushort4*)dh)[i4] = hi;
    ((ushort4*)dl)[i4] = lo;
}

// ---------------- tensor-core GEMM (+ optional LN stats) -----------------------
__global__ __launch_bounds__(256) void gemm_bf16(
    const __nv_bfloat16* __restrict__ Agh, const __nv_bfloat16* __restrict__ Agl,
    const __nv_bfloat16* __restrict__ Bgh, const __nv_bfloat16* __restrict__ Bgl,
    const float* __restrict__ bias, float* __restrict__ C, int Mvalid, int do_stats) {
    extern __shared__ char sm[];
    __shared__ float rs1[BM], rs2[BM];
    uint32_t sbase = smem_u32(sm);
    int tid = threadIdx.x, lane = tid & 31, wid = tid >> 5;
    int wm = wid & 3, wn = wid >> 2;
    int bm = blockIdx.y * BM, bn = blockIdx.x * BN;

    if (do_stats) {
        for (int i = tid; i < BM; i += 256) { rs1[i] = 0.0f; rs2[i] = 0.0f; }
    }

    float c[2][8][4];
    #pragma unroll
    for (int i = 0; i < 2; ++i)
        #pragma unroll
        for (int j = 0; j < 8; ++j)
            #pragma unroll
            for (int k = 0; k < 4; ++k) c[i][j][k] = 0.0f;

    int lrow = tid >> 2, lc = tid & 3;

    auto ld_stage = [&](int kc, int s) {
        uint32_t st = sbase + s * STAGE_B;
        #pragma unroll
        for (int t = 0; t < 2; ++t) {
            int row = lrow + t * 64;
            uint32_t doff = (uint32_t)(row * 80 + lc * 16);
            size_t ga = (size_t)(bm + row) * D_MODEL + kc * BK + lc * 8;
            size_t gb = (size_t)(bn + row) * D_MODEL + kc * BK + lc * 8;
            cp_async16(st + doff,             Agh + ga);
            cp_async16(st + MAT_B + doff,     Agl + ga);
            cp_async16(st + 2 * MAT_B + doff, Bgh + gb);
            cp_async16(st + 3 * MAT_B + doff, Bgl + gb);
        }
    };

    auto compute = [&](int s) {
        uint32_t st = sbase + s * STAGE_B;
        int arow = ((lane >> 3) & 1) * 8 + (lane & 7);
        int acolb = (lane >> 4) * 8;
        int brow = (lane >> 4) * 8 + (lane & 7);
        int bcolb = ((lane >> 3) & 1) * 8;
        #pragma unroll
        for (int ks = 0; ks < 2; ++ks) {
            uint32_t ah[2][4], al[2][4], bh[4][4], bl[4][4];
            #pragma unroll
            for (int mt = 0; mt < 2; ++mt) {
                uint32_t ad = st + (uint32_t)((wm * 32 + mt * 16 + arow) * 80 +
                                              (ks * 16 + acolb) * 2);
                LDMX4(ah[mt], ad);
                LDMX4(al[mt], ad + MAT_B);
            }
            #pragma unroll
            for (int nt2 = 0; nt2 < 4; ++nt2) {
                uint32_t bd = st + 2 * MAT_B + (uint32_t)((wn * 64 + nt2 * 16 + brow) * 80 +
                                                          (ks * 16 + bcolb) * 2);
                LDMX4(bh[nt2], bd);
                LDMX4(bl[nt2], bd + MAT_B);
            }
            #pragma unroll
            for (int mt = 0; mt < 2; ++mt)
                #pragma unroll
                for (int nt = 0; nt < 8; ++nt) {
                    int n2 = nt >> 1, pr = (nt & 1) * 2;
                    MMA_BF16(c[mt][nt], ah[mt], bh[n2][pr], bh[n2][pr + 1]);
                    MMA_BF16(c[mt][nt], ah[mt], bl[n2][pr], bl[n2][pr + 1]);
                    MMA_BF16(c[mt][nt], al[mt], bh[n2][pr], bh[n2][pr + 1]);
                }
        }
    };

    ld_stage(0, 0);
    CP_COMMIT();
    const int KC = D_MODEL / BK;
    for (int kc = 0; kc < KC; ++kc) {
        int s = kc & 1;
        if (kc < KC - 1) {
            ld_stage(kc + 1, s ^ 1);
            CP_COMMIT();
            CP_WAIT(1);
        } else {
            CP_WAIT(0);
        }
        __syncthreads();
        compute(s);
        __syncthreads();
    }

    #pragma unroll
    for (int mt = 0; mt < 2; ++mt) {
        int lr0 = wm * 32 + mt * 16 + (lane >> 2);
        int r0 = bm + lr0;
        float sA0 = 0.f, sQ0 = 0.f, sA1 = 0.f, sQ1 = 0.f;
        #pragma unroll
        for (int nt = 0; nt < 8; ++nt) {
            int col = bn + wn * 64 + nt * 8 + (lane & 3) * 2;
            float b0 = bias[col], b1 = bias[col + 1];
            float v00 = c[mt][nt][0] + b0, v01 = c[mt][nt][1] + b1;
            float v10 = c[mt][nt][2] + b0, v11 = c[mt][nt][3] + b1;
            if (r0 < Mvalid) {
                C[(size_t)r0 * D_MODEL + col]     = v00;
                C[(size_t)r0 * D_MODEL + col + 1] = v01;
            }
            if (r0 + 8 < Mvalid) {
                C[(size_t)(r0 + 8) * D_MODEL + col]     = v10;
                C[(size_t)(r0 + 8) * D_MODEL + col + 1] = v11;
            }
            sA0 += v00 + v01; sQ0 += v00 * v00 + v01 * v01;
            sA1 += v10 + v11; sQ1 += v10 * v10 + v11 * v11;
        }
        if (do_stats) {
            atomicAdd(&rs1[lr0], sA0); atomicAdd(&rs2[lr0], sQ0);
            atomicAdd(&rs1[lr0 + 8], sA1); atomicAdd(&rs2[lr0 + 8], sQ1);
        }
    }
    if (do_stats) {
        __syncthreads();
        for (int i = tid; i < BM; i += 256) {
            int r = bm + i;
            if (r < M_ROWS) {
                atomicAdd(&g_s1[r], rs1[i]);
                atomicAdd(&g_s2[r], rs2[i]);
            }
        }
    }
}

// ---------------- q GEMM + LN --------------------------------------------------
__global__ __launch_bounds__(256) void qgemm_kernel(const float* __restrict__ qx,
                                                    const float* __restrict__ qw,
                                                    const float* __restrict__ qb) {
    int gw = blockIdx.x * 8 + (threadIdx.x >> 5);
    int lane = threadIdx.x & 31;
    int row = gw / D_MODEL, col = gw - row * D_MODEL;
    const float4* x4 = (const float4*)(qx + (size_t)row * D_MODEL);
    const float4* w4 = (const float4*)(qw + (size_t)col * D_MODEL);
    float acc = 0.0f;
    #pragma unroll
    for (int i = 0; i < 6; ++i) {
        float4 a = x4[lane + 32 * i];
        float4 b = w4[lane + 32 * i];
        acc += a.x * b.x + a.y * b.y + a.z * b.z + a.w * b.w;
    }
    #pragma unroll
    for (int off = 16; off > 0; off >>= 1) acc += __shfl_xor_sync(0xffffffffu, acc, off);
    if (lane == 0) g_qpre[row * D_MODEL + col] = acc + qb[col];
}
__global__ void qln_kernel(const float* __restrict__ lw, const float* __restrict__ lb) {
    int row = blockIdx.x;
    int t = threadIdx.x;
    const float* x = g_qpre + row * D_MODEL;
    float v0 = x[t], v1 = x[t + 256], v2 = x[t + 512];
    __shared__ float red[256];
    red[t] = v0 + v1 + v2;
    __syncthreads();
    for (int s = 128; s > 0; s >>= 1) { if (t < s) red[t] += red[t + s]; __syncthreads(); }
    float mean = red[0] * (1.0f / D_MODEL);
    __syncthreads();
    float d0 = v0 - mean, d1 = v1 - mean, d2 = v2 - mean;
    red[t] = d0 * d0 + d1 * d1 + d2 * d2;
    __syncthreads();
    for (int s = 128; s > 0; s >>= 1) { if (t < s) red[t] += red[t + s]; __syncthreads(); }
    float rstd = rsqrtf(red[0] * (1.0f / D_MODEL) + LN_EPS);
    g_qln[row * D_MODEL + t]       = d0 * rstd * lw[t]       + lb[t];
    g_qln[row * D_MODEL + t + 256] = d1 * rstd * lw[t + 256] + lb[t + 256];
    g_qln[row * D_MODEL + t + 512] = d2 * rstd * lw[t + 512] + lb[t + 512];
}

// ---------------- dpos = pos[P:] - pos[:P] ------------------------------------
__global__ void dpos_kernel(const float* __restrict__ pos) {
    int i4 = blockIdx.x * blockDim.x + threadIdx.x;
    if (i4 >= NP4) return;
    float4 a = ((const float4*)pos)[NP4 + i4];
    float4 b = ((const float4*)pos)[i4];
    float4 v = make_float4(a.x - b.x, a.y - b.y, a.z - b.z, a.w - b.w);
    ((float4*)g_dpos)[i4] = v;
}

// ---------------- dsp: warp per (h,p), lanes over d ---------------------------
__global__ __launch_bounds__(256) void dsp_kernel() {
    int gw = blockIdx.x * 8 + (threadIdx.x >> 5);
    if (gw >= NUM_HEADS * P_TOK) return;
    int lane = threadIdx.x & 31;
    int h = gw / P_TOK, p = gw - h * P_TOK;
    float dp0 = g_dpos[(size_t)p * D_MODEL + h * D_HEAD + lane];
    float dp1 = g_dpos[(size_t)p * D_MODEL + h * D_HEAD + lane + 32];
    #pragma unroll
    for (int q = 0; q < NQ; ++q) {
        float acc = dp0 * g_qln[q * D_MODEL + h * D_HEAD + lane] +
                    dp1 * g_qln[q * D_MODEL + h * D_HEAD + lane + 32];
        #pragma unroll
        for (int off = 16; off > 0; off >>= 1) acc += __shfl_xor_sync(0xffffffffu, acc, off);
        if (lane == 0) g_dsp[(h * NQ + q) * 200 + p] = 0.125f * acc;
    }
}

// ---------------- attention: both halves per (b,h) block ----------------------
__global__ __launch_bounds__(256) void attn_kernel(const float* __restrict__ pos,
                                                   const float* __restrict__ lw,
                                                   const float* __restrict__ lb) {
    extern __shared__ float sm_tile[];   // [P_TOK][TILE_LD]
    int b = blockIdx.x, h = blockIdx.y;
    int tid = threadIdx.x;
    int w = tid >> 5, lane = tid & 31;

    __shared__ float4 qh4[NQ][D_HEAD / 4];
    __shared__ float sraw[NQ][200];
    __shared__ float e[NQ][200];
    __shared__ float smean[200], srstd[200];

    if (tid < P_TOK) {
        float mean = g_s1[b * P_TOK + tid] * (1.0f / D_MODEL);
        float var = g_s2[b * P_TOK + tid] * (1.0f / D_MODEL) - mean * mean;
        smean[tid] = mean;
        srstd[tid] = rsqrtf(var + LN_EPS);
    }
    for (int idx = tid; idx < NQ * (D_HEAD / 4); idx += 256) {
        int q = idx >> 4, d4 = idx & 15;
        qh4[q][d4] = ((const float4*)(g_qln + q * D_MODEL + h * D_HEAD))[d4];
    }
    __syncthreads();

    const float4* lw4 = (const float4*)(lw + h * D_HEAD);
    const float4* lb4 = (const float4*)(lb + h * D_HEAD);
    for (int idx = tid; idx < P_TOK * (D_HEAD / 4); idx += 256) {
        int p = idx >> 4, d4 = idx & 15;
        int row = b * P_TOK + p;
        float m = smean[p], r = srstd[p];
        float4 raw = ((const float4*)(g_kv + (size_t)row * D_MODEL + h * D_HEAD))[d4];
        float4 pv = ((const float4*)(pos + (size_t)p * D_MODEL + h * D_HEAD))[d4];
        float4 wv = lw4[d4], bv = lb4[d4];
        float4 out;
        out.x = (raw.x - m) * r * wv.x + bv.x + pv.x;
        out.y = (raw.y - m) * r * wv.y + bv.y + pv.y;
        out.z = (raw.z - m) * r * wv.z + bv.z + pv.z;
        out.w = (raw.w - m) * r * wv.w + bv.w + pv.w;
        *(float4*)(sm_tile + p * TILE_LD + d4 * 4) = out;
    }
    __syncthreads();

    // ---- half 0: dot + softmax ----
    {
        int q = w;
        float mx = -1e30f;
        for (int p = lane; p < P_TOK; p += 32) {
            const float4* tp4 = (const float4*)(sm_tile + p * TILE_LD);
            float s = 0.0f;
            #pragma unroll
            for (int k = 0; k < D_HEAD / 4; ++k) {
                float4 t = tp4[k];
                float4 qv = qh4[q][k];
                s += t.x * qv.x + t.y * qv.y + t.z * qv.z + t.w * qv.w;
            }
            s *= 0.125f;
            sraw[q][p] = s;
            mx = fmaxf(mx, s);
        }
        #pragma unroll
        for (int off = 16; off > 0; off >>= 1) mx = fmaxf(mx, __shfl_xor_sync(0xffffffffu, mx, off));
        float sum = 0.0f;
        for (int p = lane; p < P_TOK; p += 32) {
            float t = __expf(sraw[q][p] - mx);
            e[q][p] = t;
            sum += t;
        }
        #pragma unroll
        for (int off = 16; off > 0; off >>= 1) sum += __shfl_xor_sync(0xffffffffu, sum, off);
        if (lane == 0) {
            int idx = (b * NUM_HEADS + h) * NQ + q;
            g_m[idx] = mx;
            g_z[idx] = sum;
        }
    }
    __syncthreads();

    // ---- half 0: A ----
    for (int ii = tid; ii < NQ * D_HEAD; ii += 256) {
        int q = ii >> 6, d = ii & 63;
        float acc = 0.0f;
        const float* tcol = sm_tile + d;
        #pragma unroll 4
        for (int p = 0; p < 196; p += 4) {
            float4 ev = *(const float4*)&e[q][p];
            acc += ev.x * tcol[p * TILE_LD] + ev.y * tcol[(p + 1) * TILE_LD] +
                   ev.z * tcol[(p + 2) * TILE_LD] + ev.w * tcol[(p + 3) * TILE_LD];
        }
        acc += e[q][196] * tcol[196 * TILE_LD];
        g_a[(((size_t)b * NUM_HEADS + h) * NQ + q) * D_HEAD + d] = acc;
    }
    __syncthreads();

    // ---- switch to half 1: tile += dpos ----
    for (int idx = tid; idx < P_TOK * (D_HEAD / 4); idx += 256) {
        int p = idx >> 4, d4 = idx & 15;
        float4 dv = ((const float4*)(g_dpos + (size_t)p * D_MODEL + h * D_HEAD))[d4];
        float4* tp = (float4*)(sm_tile + p * TILE_LD + d4 * 4);
        float4 t = *tp;
        t.x += dv.x; t.y += dv.y; t.z += dv.z; t.w += dv.w;
        *tp = t;
    }
    // half 1 scores = sraw + dsp; softmax
    {
        int q = w;
        const float* dsp = g_dsp + (h * NQ + q) * 200;
        float mx = -1e30f;
        for (int p = lane; p < P_TOK; p += 32) {
            float s = sraw[q][p] + dsp[p];
            sraw[q][p] = s;
            mx = fmaxf(mx, s);
        }
        #pragma unroll
        for (int off = 16; off > 0; off >>= 1) mx = fmaxf(mx, __shfl_xor_sync(0xffffffffu, mx, off));
        float sum = 0.0f;
        for (int p = lane; p < P_TOK; p += 32) {
            float t = __expf(sraw[q][p] - mx);
            e[q][p] = t;
            sum += t;
        }
        #pragma unroll
        for (int off = 16; off > 0; off >>= 1) sum += __shfl_xor_sync(0xffffffffu, sum, off);
        if (lane == 0) {
            int idx = ((BATCH + b) * NUM_HEADS + h) * NQ + q;
            g_m[idx] = mx;
            g_z[idx] = sum;
        }
    }
    __syncthreads();

    // ---- half 1: A ----
    for (int ii = tid; ii < NQ * D_HEAD; ii += 256) {
        int q = ii >> 6, d = ii & 63;
        float acc = 0.0f;
        const float* tcol = sm_tile + d;
        #pragma unroll 4
        for (int p = 0; p < 196; p += 4) {
            float4 ev = *(const float4*)&e[q][p];
            acc += ev.x * tcol[p * TILE_LD] + ev.y * tcol[(p + 1) * TILE_LD] +
                   ev.z * tcol[(p + 2) * TILE_LD] + ev.w * tcol[(p + 3) * TILE_LD];
        }
        acc += e[q][196] * tcol[196 * TILE_LD];
        g_a[((((size_t)BATCH + b) * NUM_HEADS + h) * NQ + q) * D_HEAD + d] = acc;
    }
}

// ---------------- merge: one block per pair, loop q ---------------------------
__global__ __launch_bounds__(192) void merge_kernel() {
    int pair = blockIdx.x;
    int i = pair >> 4, j = pair & 15;
    int tid = threadIdx.x;
    __shared__ float c1s[NQ][NUM_HEADS], c2s[NQ][NUM_HEADS];
    if (tid < NQ * NUM_HEADS) {
        int q = tid / NUM_HEADS, h = tid - q * NUM_HEADS;
        int i1 = (i * NUM_HEADS + h) * NQ + q;
        int i2 = ((BATCH + j) * NUM_HEADS + h) * NQ + q;
        float m1 = g_m[i1], m2 = g_m[i2];
        float z1 = g_z[i1], z2 = g_z[i2];
        float m = fmaxf(m1, m2);
        float e1 = __expf(m1 - m), e2 = __expf(m2 - m);
        float zinv = 1.0f / (e1 * z1 + e2 * z2);
        c1s[q][h] = e1 * zinv;
        c2s[q][h] = e2 * zinv;
    }
    __syncthreads();
    int o0 = tid * 4;
    int h = o0 >> 6, d = o0 & 63;
    #pragma unroll
    for (int q = 0; q < NQ; ++q) {
        float4 a1 = *(const float4*)(g_a + (((size_t)i * NUM_HEADS + h) * NQ + q) * D_HEAD + d);
        float4 a2 = *(const float4*)(g_a + ((((size_t)BATCH + j) * NUM_HEADS + h) * NQ + q) * D_HEAD + d);
        float w1 = c1s[q][h], w2 = c2s[q][h];
        float4 v;
        v.x = w1 * a1.x - w2 * a2.x;
        v.y = w1 * a1.y - w2 * a2.y;
        v.z = w1 * a1.z - w2 * a2.z;
        v.w = w1 * a1.w - w2 * a2.w;
        ushort4 hi, lo;
        split4(v, hi, lo);
        size_t row = (size_t)pair * NQ + q;
        ((ushort4*)(g_ach + row * D_MODEL))[tid] = hi;
        ((ushort4*)(g_acl + row * D_MODEL))[tid] = lo;
    }
}

// ---------------- launch ------------------------------------------------------
extern "C" void kernel_launch(void* const* d_in, const int* in_sizes, int n_in,
                              void* d_out, int out_size) {
    const float* q_x   = (const float*)d_in[0];
    const float* kv_x  = (const float*)d_in[1];
    const float* pos   = (const float*)d_in[2];
    const float* q_w   = (const float*)d_in[3];
    const float* q_b   = (const float*)d_in[4];
    const float* kv_w  = (const float*)d_in[5];
    const float* kv_b  = (const float*)d_in[6];
    const float* out_w = (const float*)d_in[7];
    const float* out_b = (const float*)d_in[8];
    const float* lnq_w = (const float*)d_in[9];
    const float* lnq_b = (const float*)d_in[10];
    const float* lnkv_w = (const float*)d_in[11];
    const float* lnkv_b = (const float*)d_in[12];
    float* out = (float*)d_out;

    __nv_bfloat16 *p_xh, *p_xl, *p_wh, *p_wl, *p_owh, *p_owl, *p_ach, *p_acl;
    float* p_kv;
    cudaGetSymbolAddress((void**)&p_xh, g_xh);
    cudaGetSymbolAddress((void**)&p_xl, g_xl);
    cudaGetSymbolAddress((void**)&p_wh, g_wh);
    cudaGetSymbolAddress((void**)&p_wl, g_wl);
    cudaGetSymbolAddress((void**)&p_owh, g_owh);
    cudaGetSymbolAddress((void**)&p_owl, g_owl);
    cudaGetSymbolAddress((void**)&p_ach, g_ach);
    cudaGetSymbolAddress((void**)&p_acl, g_acl);
    cudaGetSymbolAddress((void**)&p_kv, g_kv);

    static cudaStream_t s1 = nullptr, s2 = nullptr;
    static cudaEvent_t evFork = nullptr, evQ = nullptr, evW = nullptr, evSP = nullptr;
    if (!s1) {
        cudaStreamCreateWithFlags(&s1, cudaStreamNonBlocking);
        cudaStreamCreateWithFlags(&s2, cudaStreamNonBlocking);
        cudaEventCreateWithFlags(&evFork, cudaEventDisableTiming);
        cudaEventCreateWithFlags(&evQ, cudaEventDisableTiming);
        cudaEventCreateWithFlags(&evW, cudaEventDisableTiming);
        cudaEventCreateWithFlags(&evSP, cudaEventDisableTiming);
        cudaFuncSetAttribute(gemm_bf16, cudaFuncAttributeMaxDynamicSharedMemorySize, 2 * STAGE_B);
        cudaFuncSetAttribute(attn_kernel, cudaFuncAttributeMaxDynamicSharedMemorySize,
                             P_TOK * TILE_LD * sizeof(float));
    }
    int gemm_smem = 2 * STAGE_B;
    int tile_bytes = P_TOK * TILE_LD * sizeof(float);

    cudaEventRecord(evFork, 0);
    cudaStreamWaitEvent(s1, evFork, 0);
    cudaStreamWaitEvent(s2, evFork, 0);

    // s1: q path
    qgemm_kernel<<<(NQ * D_MODEL) / 8, 256, 0, s1>>>(q_x, q_w, q_b);
    qln_kernel<<<NQ, 256, 0, s1>>>(lnq_w, lnq_b);
    cudaEventRecord(evQ, s1);

    // s2: dpos -> (qln) -> dsp -> out_w split
    dpos_kernel<<<(NP4 + 255) / 256, 256, 0, s2>>>(pos);
    cudaStreamWaitEvent(s2, evQ, 0);
    dsp_kernel<<<(NUM_HEADS * P_TOK + 7) / 8, 256, 0, s2>>>();
    cudaEventRecord(evSP, s2);
    splitw_kernel<<<NW4 / 256, 256, 0, s2>>>(out_w, p_owh, p_owl);
    cudaEventRecord(evW, s2);

    // main chain
    split_kv_kernel<<<(NX4 + NW4 + 255) / 256, 256>>>(kv_x, kv_w);
    gemm_bf16<<<dim3(6, 25), 256, gemm_smem>>>(p_xh, p_xl, p_wh, p_wl, kv_b, p_kv, M_ROWS, 1);
    cudaStreamWaitEvent(0, evSP, 0);
    attn_kernel<<<dim3(BATCH, NUM_HEADS), 256, tile_bytes>>>(pos, lnkv_w, lnkv_b);
    merge_kernel<<<PAIRS, 192>>>();
    cudaStreamWaitEvent(0, evW, 0);
    gemm_bf16<<<dim3(6, 16), 256, gemm_smem>>>(p_ach, p_acl, p_owh, p_owl, out_b, out, OUT_ROWS, 0);
}

// round 10
// speedup vs baseline: 1.0729x; 1.0548x over previous
#include <cuda_runtime.h>
#include <cuda_bf16.h>
#include <cstdint>
#include <math.h>

#define D_MODEL 768
#define NUM_HEADS 12
#define D_HEAD 64
#define NQ 8
#define BATCH 16
#define P_TOK 197
#define M_ROWS (BATCH * P_TOK)       // 3152
#define M_PAD 3200                   // 25 * 128
#define PAIRS (BATCH * BATCH)        // 256
#define OUT_ROWS (PAIRS * NQ)        // 2048
#define LN_EPS 1e-5f
#define TILE_LD 68

// GEMM tiling
#define BM 128
#define BN 128
#define BK 32
#define LDA 40
#define MAT_B (128 * LDA * 2)
#define STAGE_B (4 * MAT_B)          // 40960
#define NSTAGE 4

#define NX4 (M_PAD * D_MODEL / 4)
#define NW4 (D_MODEL * D_MODEL / 4)
#define NP4 (P_TOK * D_MODEL / 4)

// ---------------- scratch (device globals) ------------------------------------
__device__ float g_qpre[NQ * D_MODEL];
__device__ float g_qln[NQ * D_MODEL];
__device__ float g_kv[M_ROWS * D_MODEL];
__device__ float g_s1[M_ROWS];
__device__ float g_s2[M_ROWS];
__device__ float g_dpos[P_TOK * D_MODEL];
__device__ __nv_bfloat16 g_xh[M_PAD * D_MODEL];
__device__ __nv_bfloat16 g_xl[M_PAD * D_MODEL];
__device__ __nv_bfloat16 g_wh[D_MODEL * D_MODEL];
__device__ __nv_bfloat16 g_wl[D_MODEL * D_MODEL];
__device__ __nv_bfloat16 g_owh[D_MODEL * D_MODEL];
__device__ __nv_bfloat16 g_owl[D_MODEL * D_MODEL];
__device__ __nv_bfloat16 g_ach[OUT_ROWS * D_MODEL];
__device__ __nv_bfloat16 g_acl[OUT_ROWS * D_MODEL];
__device__ float g_m[2 * BATCH * NUM_HEADS * NQ];
__device__ float g_z[2 * BATCH * NUM_HEADS * NQ];
__device__ float g_a[2 * BATCH * NUM_HEADS * NQ * D_HEAD];

// ---------------- PTX helpers --------------------------------------------------
__device__ __forceinline__ uint32_t smem_u32(const void* p) {
    uint32_t a;
    asm("{ .reg .u64 t; cvta.to.shared.u64 t, %1; cvt.u32.u64 %0, t; }" : "=r"(a) : "l"(p));
    return a;
}
__device__ __forceinline__ void cp_async16(uint32_t s, const void* g) {
    asm volatile("cp.async.cg.shared.global [%0], [%1], 16;" :: "r"(s), "l"(g));
}
#define CP_COMMIT() asm volatile("cp.async.commit_group;")
#define CP_WAIT(n)  asm volatile("cp.async.wait_group %0;" :: "n"(n))
#define LDMX4(r, addr) \
    asm volatile("ldmatrix.sync.aligned.m8n8.x4.shared.b16 {%0,%1,%2,%3}, [%4];" \
        : "=r"((r)[0]), "=r"((r)[1]), "=r"((r)[2]), "=r"((r)[3]) : "r"(addr))
#define MMA_BF16(cr, a, b0, b1) \
    asm volatile("mma.sync.aligned.m16n8k16.row.col.f32.bf16.bf16.f32 " \
        "{%0,%1,%2,%3}, {%4,%5,%6,%7}, {%8,%9}, {%0,%1,%2,%3};" \
        : "+f"((cr)[0]), "+f"((cr)[1]), "+f"((cr)[2]), "+f"((cr)[3]) \
        : "r"((a)[0]), "r"((a)[1]), "r"((a)[2]), "r"((a)[3]), "r"(b0), "r"(b1))

// ---------------- split helpers ------------------------------------------------
__device__ __forceinline__ void split4(float4 v, ushort4& hi, ushort4& lo) {
    __nv_bfloat16 hx = __float2bfloat16_rn(v.x);
    __nv_bfloat16 hy = __float2bfloat16_rn(v.y);
    __nv_bfloat16 hz = __float2bfloat16_rn(v.z);
    __nv_bfloat16 hw = __float2bfloat16_rn(v.w);
    hi = make_ushort4(__bfloat16_as_ushort(hx), __bfloat16_as_ushort(hy),
                      __bfloat16_as_ushort(hz), __bfloat16_as_ushort(hw));
    lo = make_ushort4(
        __bfloat16_as_ushort(__float2bfloat16_rn(v.x - __bfloat162float(hx))),
        __bfloat16_as_ushort(__float2bfloat16_rn(v.y - __bfloat162float(hy))),
        __bfloat16_as_ushort(__float2bfloat16_rn(v.z - __bfloat162float(hz))),
        __bfloat16_as_ushort(__float2bfloat16_rn(v.w - __bfloat162float(hw))));
}

// split kv_x (padded) + zero LN accumulators
__global__ void splitx_kernel(const float* __restrict__ x) {
    int gi = blockIdx.x * blockDim.x + threadIdx.x;
    if (gi < M_ROWS) { g_s1[gi] = 0.0f; g_s2[gi] = 0.0f; }
    if (gi >= NX4) return;
    int row = gi / (D_MODEL / 4);
    float4 v = (row < M_ROWS) ? ((const float4*)x)[gi] : make_float4(0.f, 0.f, 0.f, 0.f);
    ushort4 hi, lo;
    split4(v, hi, lo);
    ((ushort4*)g_xh)[gi] = hi;
    ((ushort4*)g_xl)[gi] = lo;
}
__global__ void splitw_kernel(const float* __restrict__ w,
                              __nv_bfloat16* __restrict__ dh,
                              __nv_bfloat16* __restrict__ dl) {
    int i4 = blockIdx.x * blockDim.x + threadIdx.x;
    ushort4 hi, lo;
    split4(((const float4*)w)[i4], hi, lo);
    ((ushort4*)dh)[i4] = hi;
    ((ushort4*)dl)[i4] = lo;
}

// ---------------- tensor-core GEMM, 4-stage 1-sync pipeline -------------------
__global__ __launch_bounds__(256) void gemm_bf16(
    const __nv_bfloat16* __restrict__ Agh, const __nv_bfloat16* __restrict__ Agl,
    const __nv_bfloat16* __restrict__ Bgh, const __nv_bfloat16* __restrict__ Bgl,
    const float* __restrict__ bias, float* __restrict__ C, int Mvalid, int do_stats) {
    extern __shared__ char sm[];
    __shared__ float rs1[BM], rs2[BM];
    uint32_t sbase = smem_u32(sm);
    int tid = threadIdx.x, lane = tid & 31, wid = tid >> 5;
    int wm = wid & 3, wn = wid >> 2;
    int bm = blockIdx.y * BM, bn = blockIdx.x * BN;

    if (do_stats) {
        for (int i = tid; i < BM; i += 256) { rs1[i] = 0.0f; rs2[i] = 0.0f; }
    }

    float c[2][8][4];
    #pragma unroll
    for (int i = 0; i < 2; ++i)
        #pragma unroll
        for (int j = 0; j < 8; ++j)
            #pragma unroll
            for (int k = 0; k < 4; ++k) c[i][j][k] = 0.0f;

    int lrow = tid >> 2, lc = tid & 3;

    auto ld_stage = [&](int kc, int s) {
        uint32_t st = sbase + s * STAGE_B;
        #pragma unroll
        for (int t = 0; t < 2; ++t) {
            int row = lrow + t * 64;
            uint32_t doff = (uint32_t)(row * 80 + lc * 16);
            size_t ga = (size_t)(bm + row) * D_MODEL + kc * BK + lc * 8;
            size_t gb = (size_t)(bn + row) * D_MODEL + kc * BK + lc * 8;
            cp_async16(st + doff,             Agh + ga);
            cp_async16(st + MAT_B + doff,     Agl + ga);
            cp_async16(st + 2 * MAT_B + doff, Bgh + gb);
            cp_async16(st + 3 * MAT_B + doff, Bgl + gb);
        }
    };

    auto compute = [&](int s) {
        uint32_t st = sbase + s * STAGE_B;
        int arow = ((lane >> 3) & 1) * 8 + (lane & 7);
        int acolb = (lane >> 4) * 8;
        int brow = (lane >> 4) * 8 + (lane & 7);
        int bcolb = ((lane >> 3) & 1) * 8;
        #pragma unroll
        for (int ks = 0; ks < 2; ++ks) {
            uint32_t ah[2][4], al[2][4], bh[4][4], bl[4][4];
            #pragma unroll
            for (int mt = 0; mt < 2; ++mt) {
                uint32_t ad = st + (uint32_t)((wm * 32 + mt * 16 + arow) * 80 +
                                              (ks * 16 + acolb) * 2);
                LDMX4(ah[mt], ad);
                LDMX4(al[mt], ad + MAT_B);
            }
            #pragma unroll
            for (int nt2 = 0; nt2 < 4; ++nt2) {
                uint32_t bd = st + 2 * MAT_B + (uint32_t)((wn * 64 + nt2 * 16 + brow) * 80 +
                                                          (ks * 16 + bcolb) * 2);
                LDMX4(bh[nt2], bd);
                LDMX4(bl[nt2], bd + MAT_B);
            }
            #pragma unroll
            for (int mt = 0; mt < 2; ++mt)
                #pragma unroll
                for (int nt = 0; nt < 8; ++nt) {
                    int n2 = nt >> 1, pr = (nt & 1) * 2;
                    MMA_BF16(c[mt][nt], ah[mt], bh[n2][pr], bh[n2][pr + 1]);
                    MMA_BF16(c[mt][nt], ah[mt], bl[n2][pr], bl[n2][pr + 1]);
                    MMA_BF16(c[mt][nt], al[mt], bh[n2][pr], bh[n2][pr + 1]);
                }
        }
    };

    const int KC = D_MODEL / BK;   // 24
    #pragma unroll
    for (int s = 0; s < NSTAGE - 1; ++s) {
        ld_stage(s, s);
        CP_COMMIT();
    }
    for (int kc = 0; kc < KC; ++kc) {
        int s = kc & (NSTAGE - 1);
        CP_WAIT(NSTAGE - 2);
        __syncthreads();
        compute(s);
        if (kc + NSTAGE - 1 < KC) ld_stage(kc + NSTAGE - 1, (kc + NSTAGE - 1) & (NSTAGE - 1));
        CP_COMMIT();
    }

    #pragma unroll
    for (int mt = 0; mt < 2; ++mt) {
        int lr0 = wm * 32 + mt * 16 + (lane >> 2);
        int r0 = bm + lr0;
        float sA0 = 0.f, sQ0 = 0.f, sA1 = 0.f, sQ1 = 0.f;
        #pragma unroll
        for (int nt = 0; nt < 8; ++nt) {
            int col = bn + wn * 64 + nt * 8 + (lane & 3) * 2;
            float b0 = bias[col], b1 = bias[col + 1];
            float v00 = c[mt][nt][0] + b0, v01 = c[mt][nt][1] + b1;
            float v10 = c[mt][nt][2] + b0, v11 = c[mt][nt][3] + b1;
            if (r0 < Mvalid) {
                C[(size_t)r0 * D_MODEL + col]     = v00;
                C[(size_t)r0 * D_MODEL + col + 1] = v01;
            }
            if (r0 + 8 < Mvalid) {
                C[(size_t)(r0 + 8) * D_MODEL + col]     = v10;
                C[(size_t)(r0 + 8) * D_MODEL + col + 1] = v11;
            }
            sA0 += v00 + v01; sQ0 += v00 * v00 + v01 * v01;
            sA1 += v10 + v11; sQ1 += v10 * v10 + v11 * v11;
        }
        if (do_stats) {
            atomicAdd(&rs1[lr0], sA0); atomicAdd(&rs2[lr0], sQ0);
            atomicAdd(&rs1[lr0 + 8], sA1); atomicAdd(&rs2[lr0 + 8], sQ1);
        }
    }
    if (do_stats) {
        __syncthreads();
        for (int i = tid; i < BM; i += 256) {
            int r = bm + i;
            if (r < M_ROWS) {
                atomicAdd(&g_s1[r], rs1[i]);
                atomicAdd(&g_s2[r], rs2[i]);
            }
        }
    }
}

// ---------------- q GEMM + LN --------------------------------------------------
__global__ __launch_bounds__(256) void qgemm_kernel(const float* __restrict__ qx,
                                                    const float* __restrict__ qw,
                                                    const float* __restrict__ qb) {
    int gw = blockIdx.x * 8 + (threadIdx.x >> 5);
    int lane = threadIdx.x & 31;
    int row = gw / D_MODEL, col = gw - row * D_MODEL;
    const float4* x4 = (const float4*)(qx + (size_t)row * D_MODEL);
    const float4* w4 = (const float4*)(qw + (size_t)col * D_MODEL);
    float acc = 0.0f;
    #pragma unroll
    for (int i = 0; i < 6; ++i) {
        float4 a = x4[lane + 32 * i];
        float4 b = w4[lane + 32 * i];
        acc += a.x * b.x + a.y * b.y + a.z * b.z + a.w * b.w;
    }
    #pragma unroll
    for (int off = 16; off > 0; off >>= 1) acc += __shfl_xor_sync(0xffffffffu, acc, off);
    if (lane == 0) g_qpre[row * D_MODEL + col] = acc + qb[col];
}
__global__ void qln_kernel(const float* __restrict__ lw, const float* __restrict__ lb) {
    int row = blockIdx.x;
    int t = threadIdx.x;
    const float* x = g_qpre + row * D_MODEL;
    float v0 = x[t], v1 = x[t + 256], v2 = x[t + 512];
    __shared__ float red[256];
    red[t] = v0 + v1 + v2;
    __syncthreads();
    for (int s = 128; s > 0; s >>= 1) { if (t < s) red[t] += red[t + s]; __syncthreads(); }
    float mean = red[0] * (1.0f / D_MODEL);
    __syncthreads();
    float d0 = v0 - mean, d1 = v1 - mean, d2 = v2 - mean;
    red[t] = d0 * d0 + d1 * d1 + d2 * d2;
    __syncthreads();
    for (int s = 128; s > 0; s >>= 1) { if (t < s) red[t] += red[t + s]; __syncthreads(); }
    float rstd = rsqrtf(red[0] * (1.0f / D_MODEL) + LN_EPS);
    g_qln[row * D_MODEL + t]       = d0 * rstd * lw[t]       + lb[t];
    g_qln[row * D_MODEL + t + 256] = d1 * rstd * lw[t + 256] + lb[t + 256];
    g_qln[row * D_MODEL + t + 512] = d2 * rstd * lw[t + 512] + lb[t + 512];
}

// ---------------- dpos = pos[P:] - pos[:P] ------------------------------------
__global__ void dpos_kernel(const float* __restrict__ pos) {
    int i4 = blockIdx.x * blockDim.x + threadIdx.x;
    if (i4 >= NP4) return;
    float4 a = ((const float4*)pos)[NP4 + i4];
    float4 b = ((const float4*)pos)[i4];
    ((float4*)g_dpos)[i4] = make_float4(a.x - b.x, a.y - b.y, a.z - b.z, a.w - b.w);
}

// ---------------- attention: both halves per (b,h) block ----------------------
__global__ __launch_bounds__(256) void attn_kernel(const float* __restrict__ pos,
                                                   const float* __restrict__ lw,
                                                   const float* __restrict__ lb) {
    extern __shared__ float sm_tile[];   // [P_TOK][TILE_LD]
    int b = blockIdx.x, h = blockIdx.y;
    int tid = threadIdx.x;
    int w = tid >> 5, lane = tid & 31;

    __shared__ float4 qh4[NQ][D_HEAD / 4];
    __shared__ float e[NQ][200];
    __shared__ float smean[200], srstd[200];

    if (tid < P_TOK) {
        float mean = g_s1[b * P_TOK + tid] * (1.0f / D_MODEL);
        float var = g_s2[b * P_TOK + tid] * (1.0f / D_MODEL) - mean * mean;
        smean[tid] = mean;
        srstd[tid] = rsqrtf(var + LN_EPS);
    }
    for (int idx = tid; idx < NQ * (D_HEAD / 4); idx += 256) {
        int q = idx >> 4, d4 = idx & 15;
        qh4[q][d4] = ((const float4*)(g_qln + q * D_MODEL + h * D_HEAD))[d4];
    }
    __syncthreads();

    const float4* lw4 = (const float4*)(lw + h * D_HEAD);
    const float4* lb4 = (const float4*)(lb + h * D_HEAD);
    for (int idx = tid; idx < P_TOK * (D_HEAD / 4); idx += 256) {
        int p = idx >> 4, d4 = idx & 15;
        int row = b * P_TOK + p;
        float m = smean[p], r = srstd[p];
        float4 raw = ((const float4*)(g_kv + (size_t)row * D_MODEL + h * D_HEAD))[d4];
        float4 pv = ((const float4*)(pos + (size_t)p * D_MODEL + h * D_HEAD))[d4];
        float4 wv = lw4[d4], bv = lb4[d4];
        float4 out;
        out.x = (raw.x - m) * r * wv.x + bv.x + pv.x;
        out.y = (raw.y - m) * r * wv.y + bv.y + pv.y;
        out.z = (raw.z - m) * r * wv.z + bv.z + pv.z;
        out.w = (raw.w - m) * r * wv.w + bv.w + pv.w;
        *(float4*)(sm_tile + p * TILE_LD + d4 * 4) = out;
    }
    __syncthreads();

    #pragma unroll
    for (int half = 0; half < 2; ++half) {
        if (half == 1) {
            // tile += dpos (switch to half 1)
            for (int idx = tid; idx < P_TOK * (D_HEAD / 4); idx += 256) {
                int p = idx >> 4, d4 = idx & 15;
                float4 dv = ((const float4*)(g_dpos + (size_t)p * D_MODEL + h * D_HEAD))[d4];
                float4* tp = (float4*)(sm_tile + p * TILE_LD + d4 * 4);
                float4 t = *tp;
                t.x += dv.x; t.y += dv.y; t.z += dv.z; t.w += dv.w;
                *tp = t;
            }
            __syncthreads();
        }
        // dot + softmax: one warp per q
        {
            int q = w;
            float mx = -1e30f;
            for (int p = lane; p < P_TOK; p += 32) {
                const float4* tp4 = (const float4*)(sm_tile + p * TILE_LD);
                float s = 0.0f;
                #pragma unroll
                for (int k = 0; k < D_HEAD / 4; ++k) {
                    float4 t = tp4[k];
                    float4 qv = qh4[q][k];
                    s += t.x * qv.x + t.y * qv.y + t.z * qv.z + t.w * qv.w;
                }
                s *= 0.125f;
                e[q][p] = s;
                mx = fmaxf(mx, s);
            }
            #pragma unroll
            for (int off = 16; off > 0; off >>= 1)
                mx = fmaxf(mx, __shfl_xor_sync(0xffffffffu, mx, off));
            float sum = 0.0f;
            for (int p = lane; p < P_TOK; p += 32) {
                float t = __expf(e[q][p] - mx);
                e[q][p] = t;
                sum += t;
            }
            #pragma unroll
            for (int off = 16; off > 0; off >>= 1)
                sum += __shfl_xor_sync(0xffffffffu, sum, off);
            if (lane == 0) {
                int idx = ((half * BATCH + b) * NUM_HEADS + h) * NQ + q;
                g_m[idx] = mx;
                g_z[idx] = sum;
            }
        }
        __syncthreads();

        // A[q][d] = sum_p e[q][p] * tile[p][d]
        for (int ii = tid; ii < NQ * D_HEAD; ii += 256) {
            int q = ii >> 6, d = ii & 63;
            float acc = 0.0f;
            const float* tcol = sm_tile + d;
            #pragma unroll 4
            for (int p = 0; p < 196; p += 4) {
                float4 ev = *(const float4*)&e[q][p];
                acc += ev.x * tcol[p * TILE_LD] + ev.y * tcol[(p + 1) * TILE_LD] +
                       ev.z * tcol[(p + 2) * TILE_LD] + ev.w * tcol[(p + 3) * TILE_LD];
            }
            acc += e[q][196] * tcol[196 * TILE_LD];
            g_a[((((size_t)half * BATCH + b) * NUM_HEADS + h) * NQ + q) * D_HEAD + d] = acc;
        }
        __syncthreads();
    }
}

// ---------------- merge: one block per pair, loop q ---------------------------
__global__ __launch_bounds__(192) void merge_kernel() {
    int pair = blockIdx.x;
    int i = pair >> 4, j = pair & 15;
    int tid = threadIdx.x;
    __shared__ float c1s[NQ][NUM_HEADS], c2s[NQ][NUM_HEADS];
    if (tid < NQ * NUM_HEADS) {
        int q = tid / NUM_HEADS, h = tid - q * NUM_HEADS;
        int i1 = (i * NUM_HEADS + h) * NQ + q;
        int i2 = ((BATCH + j) * NUM_HEADS + h) * NQ + q;
        float m1 = g_m[i1], m2 = g_m[i2];
        float z1 = g_z[i1], z2 = g_z[i2];
        float m = fmaxf(m1, m2);
        float e1 = __expf(m1 - m), e2 = __expf(m2 - m);
        float zinv = 1.0f / (e1 * z1 + e2 * z2);
        c1s[q][h] = e1 * zinv;
        c2s[q][h] = e2 * zinv;
    }
    __syncthreads();
    int o0 = tid * 4;
    int h = o0 >> 6, d = o0 & 63;
    #pragma unroll
    for (int q = 0; q < NQ; ++q) {
        float4 a1 = *(const float4*)(g_a + (((size_t)i * NUM_HEADS + h) * NQ + q) * D_HEAD + d);
        float4 a2 = *(const float4*)(g_a + ((((size_t)BATCH + j) * NUM_HEADS + h) * NQ + q) * D_HEAD + d);
        float w1 = c1s[q][h], w2 = c2s[q][h];
        float4 v;
        v.x = w1 * a1.x - w2 * a2.x;
        v.y = w1 * a1.y - w2 * a2.y;
        v.z = w1 * a1.z - w2 * a2.z;
        v.w = w1 * a1.w - w2 * a2.w;
        ushort4 hi, lo;
        split4(v, hi, lo);
        size_t row = (size_t)pair * NQ + q;
        ((ushort4*)(g_ach + row * D_MODEL))[tid] = hi;
        ((ushort4*)(g_acl + row * D_MODEL))[tid] = lo;
    }
}

// ---------------- launch ------------------------------------------------------
extern "C" void kernel_launch(void* const* d_in, const int* in_sizes, int n_in,
                              void* d_out, int out_size) {
    const float* q_x   = (const float*)d_in[0];
    const float* kv_x  = (const float*)d_in[1];
    const float* pos   = (const float*)d_in[2];
    const float* q_w   = (const float*)d_in[3];
    const float* q_b   = (const float*)d_in[4];
    const float* kv_w  = (const float*)d_in[5];
    const float* kv_b  = (const float*)d_in[6];
    const float* out_w = (const float*)d_in[7];
    const float* out_b = (const float*)d_in[8];
    const float* lnq_w = (const float*)d_in[9];
    const float* lnq_b = (const float*)d_in[10];
    const float* lnkv_w = (const float*)d_in[11];
    const float* lnkv_b = (const float*)d_in[12];
    float* out = (float*)d_out;

    __nv_bfloat16 *p_xh, *p_xl, *p_wh, *p_wl, *p_owh, *p_owl, *p_ach, *p_acl;
    float* p_kv;
    cudaGetSymbolAddress((void**)&p_xh, g_xh);
    cudaGetSymbolAddress((void**)&p_xl, g_xl);
    cudaGetSymbolAddress((void**)&p_wh, g_wh);
    cudaGetSymbolAddress((void**)&p_wl, g_wl);
    cudaGetSymbolAddress((void**)&p_owh, g_owh);
    cudaGetSymbolAddress((void**)&p_owl, g_owl);
    cudaGetSymbolAddress((void**)&p_ach, g_ach);
    cudaGetSymbolAddress((void**)&p_acl, g_acl);
    cudaGetSymbolAddress((void**)&p_kv, g_kv);

    static cudaStream_t s1 = nullptr, s2 = nullptr;
    static cudaEvent_t evFork = nullptr, evQ = nullptr, evW = nullptr, evKW = nullptr, evDP = nullptr;
    if (!s1) {
        cudaStreamCreateWithFlags(&s1, cudaStreamNonBlocking);
        cudaStreamCreateWithFlags(&s2, cudaStreamNonBlocking);
        cudaEventCreateWithFlags(&evFork, cudaEventDisableTiming);
        cudaEventCreateWithFlags(&evQ, cudaEventDisableTiming);
        cudaEventCreateWithFlags(&evW, cudaEventDisableTiming);
        cudaEventCreateWithFlags(&evKW, cudaEventDisableTiming);
        cudaEventCreateWithFlags(&evDP, cudaEventDisableTiming);
        cudaFuncSetAttribute(gemm_bf16, cudaFuncAttributeMaxDynamicSharedMemorySize,
                             NSTAGE * STAGE_B);
        cudaFuncSetAttribute(attn_kernel, cudaFuncAttributeMaxDynamicSharedMemorySize,
                             P_TOK * TILE_LD * sizeof(float));
    }
    int gemm_smem = NSTAGE * STAGE_B;                  // 163840
    int tile_bytes = P_TOK * TILE_LD * sizeof(float);  // 53584

    cudaEventRecord(evFork, 0);
    cudaStreamWaitEvent(s1, evFork, 0);
    cudaStreamWaitEvent(s2, evFork, 0);

    // s1: q path
    qgemm_kernel<<<(NQ * D_MODEL) / 8, 256, 0, s1>>>(q_x, q_w, q_b);
    qln_kernel<<<NQ, 256, 0, s1>>>(lnq_w, lnq_b);
    cudaEventRecord(evQ, s1);

    // s2: kv_w split (for gemm1), dpos, out_w split (for gemm2)
    splitw_kernel<<<NW4 / 256, 256, 0, s2>>>(kv_w, p_wh, p_wl);
    cudaEventRecord(evKW, s2);
    dpos_kernel<<<(NP4 + 255) / 256, 256, 0, s2>>>(pos);
    cudaEventRecord(evDP, s2);
    splitw_kernel<<<NW4 / 256, 256, 0, s2>>>(out_w, p_owh, p_owl);
    cudaEventRecord(evW, s2);

    // main chain
    splitx_kernel<<<(NX4 + 255) / 256, 256>>>(kv_x);
    cudaStreamWaitEvent(0, evKW, 0);
    gemm_bf16<<<dim3(6, 25), 256, gemm_smem>>>(p_xh, p_xl, p_wh, p_wl, kv_b, p_kv, M_ROWS, 1);
    cudaStreamWaitEvent(0, evQ, 0);
    cudaStreamWaitEvent(0, evDP, 0);
    attn_kernel<<<dim3(BATCH, NUM_HEADS), 256, tile_bytes>>>(pos, lnkv_w, lnkv_b);
    merge_kernel<<<PAIRS, 192>>>();
    cudaStreamWaitEvent(0, evW, 0);
    gemm_bf16<<<dim3(6, 16), 256, gemm_smem>>>(p_ach, p_acl, p_owh, p_owl, out_b, out, OUT_ROWS, 0);
}